// round 8
// baseline (speedup 1.0000x reference)
#include <cuda_runtime.h>

// Deform_Conv_V1: fused offset-conv + deformable conv + ReLU.
// B=8, Cin=32, H=W=160, Cout=32, K=3, PAD=1.
// Inputs: x (8,32,160,160), w_off (18,32,3,3), b_off (18,), w_dcn (32,32,3,3)
// Output: (8,32,160,160) fp32.
//
// R8: x transposed to NHWC once (tiled transpose kernel) so every bilinear
//     corner is one contiguous 128B line -> 8 x LDG.128 instead of 32 scattered
//     LDG.32. Keeps R5-7 wins: weights in __constant__, 2 px/thread, FFMA2,
//     offset stash in smem, launch_bounds(128,4).

#define Hn  160
#define Wn  160
#define CIN 32
#define COUT 32
#define HWs (Hn * Wn)
#define NPIX (8 * HWs)

#define WDCN_T_ELEMS (9 * 32 * 32)   // [k][c][o]         = 9216
#define WOFF_T_ELEMS (9 * 32 * 20)   // [k][c][oc pad 20] = 5760

__constant__ float c_wdcn[WDCN_T_ELEMS];   // 36 KB
__constant__ float c_woff[WOFF_T_ELEMS];   // 22.5 KB
__device__ float g_stage[WDCN_T_ELEMS + WOFF_T_ELEMS];
__device__ __align__(128) float g_xnhwc[NPIX * CIN];   // 26.2 MB scratch

typedef unsigned long long u64;

__device__ __forceinline__ u64 pack2(float a, float b) {
    u64 r;
    asm("mov.b64 %0, {%1, %2};" : "=l"(r) : "f"(a), "f"(b));
    return r;
}
__device__ __forceinline__ void unpack2(u64 v, float& a, float& b) {
    asm("mov.b64 {%0, %1}, %2;" : "=f"(a), "=f"(b) : "l"(v));
}
__device__ __forceinline__ void ffma2(u64& d, u64 a, u64 b) {
    asm("fma.rn.f32x2 %0, %1, %2, %0;" : "+l"(d) : "l"(a), "l"(b));
}

__global__ void prep_kernel(const float* __restrict__ w_off,
                            const float* __restrict__ w_dcn)
{
    const int i = blockIdx.x * 256 + threadIdx.x;
    if (i < WDCN_T_ELEMS) {
        int k = i >> 10;
        int r = i & 1023;
        int c = r >> 5;
        int o = r & 31;
        g_stage[i] = w_dcn[o * 288 + c * 9 + k];
    }
    if (i < WOFF_T_ELEMS) {
        int k = i / 640;
        int r = i - k * 640;
        int c = r / 20;
        int oc = r - c * 20;
        g_stage[WDCN_T_ELEMS + i] = (oc < 18) ? w_off[oc * 288 + c * 9 + k] : 0.0f;
    }
}

// NCHW -> NHWC tiled transpose: block handles 64 consecutive pixels x 32 channels.
__global__ __launch_bounds__(256)
void transpose_kernel(const float* __restrict__ x)
{
    __shared__ float tile[32][65];
    const int t = threadIdx.x;
    const int blockPix = blockIdx.x * 64;           // global pixel base (never straddles b: 25600 % 64 == 0)
    const int b   = blockPix / HWs;
    const int hw0 = blockPix - b * HWs;
    const float* xp = x + (size_t)b * CIN * HWs + hw0;

#pragma unroll
    for (int i = 0; i < 8; i++) {
        int idx = i * 256 + t;
        int c = idx >> 6;
        int p = idx & 63;
        tile[c][p] = xp[c * HWs + p];
    }
    __syncthreads();
    float* op = g_xnhwc + (size_t)blockPix * CIN;
#pragma unroll
    for (int i = 0; i < 8; i++) {
        int idx = i * 256 + t;
        int p = idx >> 5;
        int c = idx & 31;
        op[idx] = tile[c][p];
    }
}

__global__ __launch_bounds__(128, 4)
void dcn_fused_kernel(const float* __restrict__ b_off,
                      float* __restrict__ out)
{
    __shared__ u64 offs_s[2][128][9];   // thread-private stash, no syncs needed

    const int tid = threadIdx.x;
    const int pairIdx = blockIdx.x * 128 + tid;   // 0 .. 102399
    const int PAIRS_PER_IMG = HWs / 2;            // 12800
    const int b   = pairIdx / PAIRS_PER_IMG;
    const int rem = pairIdx - b * PAIRS_PER_IMG;
    const int h   = rem / (Wn / 2);
    const int w0  = (rem - h * (Wn / 2)) * 2;
    const char* xbase = (const char*)g_xnhwc + (size_t)b * HWs * (CIN * 4);  // 128 B per pixel

    // ------------- Stage 1: offset conv -------------
    {
        u64 o2a[9], o2b[9];
#pragma unroll
        for (int p = 0; p < 9; p++) {
            u64 bv = pack2(__ldg(&b_off[2 * p]), __ldg(&b_off[2 * p + 1]));
            o2a[p] = bv;
            o2b[p] = bv;
        }

#pragma unroll
        for (int k = 0; k < 9; k++) {
            const int ky = k / 3;
            const int kx = k - 3 * ky;
            const int yy = h - 1 + ky;
            if (yy >= 0 && yy < Hn) {
                const int xx0 = w0 - 1 + kx;
                const int xx1 = xx0 + 1;
                const bool v0 = (xx0 >= 0) && (xx0 < Wn);
                const bool v1 = (xx1 >= 0) && (xx1 < Wn);
                const char* pA = xbase + (size_t)(yy * Wn + xx0) * 128;
                const char* pB = pA + 128;
#pragma unroll
                for (int j = 0; j < 8; j++) {
                    float4 A = v0 ? *(const float4*)(pA + j * 16) : make_float4(0.f, 0.f, 0.f, 0.f);
                    float4 B = v1 ? *(const float4*)(pB + j * 16) : make_float4(0.f, 0.f, 0.f, 0.f);
                    const float Aa[4] = {A.x, A.y, A.z, A.w};
                    const float Ba[4] = {B.x, B.y, B.z, B.w};
#pragma unroll
                    for (int cc = 0; cc < 4; cc++) {
                        const int c = 4 * j + cc;
                        const u64 xa  = pack2(Aa[cc], Aa[cc]);
                        const u64 xbv = pack2(Ba[cc], Ba[cc]);
                        const ulonglong2* wc = (const ulonglong2*)(c_woff + k * 640 + c * 20);
#pragma unroll
                        for (int jj = 0; jj < 4; jj++) {
                            ulonglong2 q = wc[jj];
                            ffma2(o2a[2 * jj],     xa,  q.x);
                            ffma2(o2a[2 * jj + 1], xa,  q.y);
                            ffma2(o2b[2 * jj],     xbv, q.x);
                            ffma2(o2b[2 * jj + 1], xbv, q.y);
                        }
                        ulonglong2 q4 = wc[4];
                        ffma2(o2a[8], xa,  q4.x);
                        ffma2(o2b[8], xbv, q4.x);
                    }
                }
            }
        }

#pragma unroll
        for (int p = 0; p < 9; p++) {
            offs_s[0][tid][p] = o2a[p];
            offs_s[1][tid][p] = o2b[p];
        }
    }

    // ------------- Stage 2: deformable conv -------------
    u64 acca[16], accb[16];
#pragma unroll
    for (int m = 0; m < 16; m++) { acca[m] = 0ULL; accb[m] = 0ULL; }

#pragma unroll
    for (int k = 0; k < 9; k++) {
        const int ky = k / 3;
        const int kx = k - 3 * ky;

        float aw00, aw01, aw10, aw11; int a00, a01, a10, a11;
        {
            float dy, dx; unpack2(offs_s[0][tid][k], dy, dx);
            const float py = (float)(h - 1 + ky) + dy;
            const float px = (float)(w0 - 1 + kx) + dx;
            const float y0f = floorf(py), x0f = floorf(px);
            const float wy1 = py - y0f,  wx1 = px - x0f;
            const float wy0 = 1.0f - wy1, wx0 = 1.0f - wx1;
            const float y1f = y0f + 1.0f, x1f = x0f + 1.0f;
            const bool vy0 = (y0f >= 0.0f) && (y0f <= (float)(Hn - 1));
            const bool vy1 = (y1f >= 0.0f) && (y1f <= (float)(Hn - 1));
            const bool vx0 = (x0f >= 0.0f) && (x0f <= (float)(Wn - 1));
            const bool vx1 = (x1f >= 0.0f) && (x1f <= (float)(Wn - 1));
            aw00 = (vy0 && vx0) ? wy0 * wx0 : 0.0f;
            aw01 = (vy0 && vx1) ? wy0 * wx1 : 0.0f;
            aw10 = (vy1 && vx0) ? wy1 * wx0 : 0.0f;
            aw11 = (vy1 && vx1) ? wy1 * wx1 : 0.0f;
            const int iy0 = min(max((int)y0f, 0), Hn - 1);
            const int iy1 = min(max((int)y1f, 0), Hn - 1);
            const int ix0 = min(max((int)x0f, 0), Wn - 1);
            const int ix1 = min(max((int)x1f, 0), Wn - 1);
            a00 = iy0 * Wn + ix0; a01 = iy0 * Wn + ix1;
            a10 = iy1 * Wn + ix0; a11 = iy1 * Wn + ix1;
        }
        float bw00, bw01, bw10, bw11; int b00, b01, b10, b11;
        {
            float dy, dx; unpack2(offs_s[1][tid][k], dy, dx);
            const float py = (float)(h - 1 + ky) + dy;
            const float px = (float)(w0 + kx) + dx;
            const float y0f = floorf(py), x0f = floorf(px);
            const float wy1 = py - y0f,  wx1 = px - x0f;
            const float wy0 = 1.0f - wy1, wx0 = 1.0f - wx1;
            const float y1f = y0f + 1.0f, x1f = x0f + 1.0f;
            const bool vy0 = (y0f >= 0.0f) && (y0f <= (float)(Hn - 1));
            const bool vy1 = (y1f >= 0.0f) && (y1f <= (float)(Hn - 1));
            const bool vx0 = (x0f >= 0.0f) && (x0f <= (float)(Wn - 1));
            const bool vx1 = (x1f >= 0.0f) && (x1f <= (float)(Wn - 1));
            bw00 = (vy0 && vx0) ? wy0 * wx0 : 0.0f;
            bw01 = (vy0 && vx1) ? wy0 * wx1 : 0.0f;
            bw10 = (vy1 && vx0) ? wy1 * wx0 : 0.0f;
            bw11 = (vy1 && vx1) ? wy1 * wx1 : 0.0f;
            const int iy0 = min(max((int)y0f, 0), Hn - 1);
            const int iy1 = min(max((int)y1f, 0), Hn - 1);
            const int ix0 = min(max((int)x0f, 0), Wn - 1);
            const int ix1 = min(max((int)x1f, 0), Wn - 1);
            b00 = iy0 * Wn + ix0; b01 = iy0 * Wn + ix1;
            b10 = iy1 * Wn + ix0; b11 = iy1 * Wn + ix1;
        }

        const char* pa00 = xbase + (size_t)a00 * 128;
        const char* pa01 = xbase + (size_t)a01 * 128;
        const char* pa10 = xbase + (size_t)a10 * 128;
        const char* pa11 = xbase + (size_t)a11 * 128;
        const char* pb00 = xbase + (size_t)b00 * 128;
        const char* pb01 = xbase + (size_t)b01 * 128;
        const char* pb10 = xbase + (size_t)b10 * 128;
        const char* pb11 = xbase + (size_t)b11 * 128;

#pragma unroll
        for (int j = 0; j < 8; j++) {
            const float4 qa00 = *(const float4*)(pa00 + j * 16);
            const float4 qa01 = *(const float4*)(pa01 + j * 16);
            const float4 qa10 = *(const float4*)(pa10 + j * 16);
            const float4 qa11 = *(const float4*)(pa11 + j * 16);
            const float4 qb00 = *(const float4*)(pb00 + j * 16);
            const float4 qb01 = *(const float4*)(pb01 + j * 16);
            const float4 qb10 = *(const float4*)(pb10 + j * 16);
            const float4 qb11 = *(const float4*)(pb11 + j * 16);
            const float a00v[4] = {qa00.x, qa00.y, qa00.z, qa00.w};
            const float a01v[4] = {qa01.x, qa01.y, qa01.z, qa01.w};
            const float a10v[4] = {qa10.x, qa10.y, qa10.z, qa10.w};
            const float a11v[4] = {qa11.x, qa11.y, qa11.z, qa11.w};
            const float b00v[4] = {qb00.x, qb00.y, qb00.z, qb00.w};
            const float b01v[4] = {qb01.x, qb01.y, qb01.z, qb01.w};
            const float b10v[4] = {qb10.x, qb10.y, qb10.z, qb10.w};
            const float b11v[4] = {qb11.x, qb11.y, qb11.z, qb11.w};
#pragma unroll
            for (int cc = 0; cc < 4; cc++) {
                const int c = 4 * j + cc;
                const float va = fmaf(aw00, a00v[cc],
                                fmaf(aw01, a01v[cc],
                                fmaf(aw10, a10v[cc],
                                     aw11 * a11v[cc])));
                const float vb = fmaf(bw00, b00v[cc],
                                fmaf(bw01, b01v[cc],
                                fmaf(bw10, b10v[cc],
                                     bw11 * b11v[cc])));
                const u64 va2 = pack2(va, va);
                const u64 vb2 = pack2(vb, vb);
                const ulonglong2* wc = (const ulonglong2*)(c_wdcn + k * 1024 + c * 32);
#pragma unroll
                for (int jj = 0; jj < 8; jj++) {
                    ulonglong2 q = wc[jj];
                    ffma2(acca[2 * jj],     va2, q.x);
                    ffma2(acca[2 * jj + 1], va2, q.y);
                    ffma2(accb[2 * jj],     vb2, q.x);
                    ffma2(accb[2 * jj + 1], vb2, q.y);
                }
            }
        }
    }

    // ------------- Epilogue: ReLU + coalesced float2 stores (NCHW out) -------------
    float* ob = out + (size_t)b * COUT * HWs + h * Wn + w0;
#pragma unroll
    for (int m = 0; m < 16; m++) {
        float a0, a1, c0, c1;
        unpack2(acca[m], a0, a1);
        unpack2(accb[m], c0, c1);
        float2 r0, r1;
        r0.x = fmaxf(a0, 0.0f); r0.y = fmaxf(c0, 0.0f);
        r1.x = fmaxf(a1, 0.0f); r1.y = fmaxf(c1, 0.0f);
        *(float2*)(ob + (2 * m)     * HWs) = r0;
        *(float2*)(ob + (2 * m + 1) * HWs) = r1;
    }
}

extern "C" void kernel_launch(void* const* d_in, const int* in_sizes, int n_in,
                              void* d_out, int out_size)
{
    const float* x     = (const float*)d_in[0];
    const float* w_off = (const float*)d_in[1];
    const float* b_off = (const float*)d_in[2];
    const float* w_dcn = (const float*)d_in[3];
    float* out = (float*)d_out;

    void* stage_dev = nullptr;
    cudaGetSymbolAddress(&stage_dev, g_stage);

    prep_kernel<<<(WDCN_T_ELEMS + 255) / 256, 256>>>(w_off, w_dcn);
    transpose_kernel<<<NPIX / 64, 256>>>(x);

    cudaMemcpyToSymbolAsync(c_wdcn, stage_dev,
                            WDCN_T_ELEMS * sizeof(float), 0,
                            cudaMemcpyDeviceToDevice, 0);
    cudaMemcpyToSymbolAsync(c_woff, (const char*)stage_dev + WDCN_T_ELEMS * sizeof(float),
                            WOFF_T_ELEMS * sizeof(float), 0,
                            cudaMemcpyDeviceToDevice, 0);

    const int total_pairs = NPIX / 2;           // 102400
    const int threads = 128;
    const int blocks = total_pairs / threads;   // 800
    dcn_fused_kernel<<<blocks, threads>>>(b_off, out);
}

// round 10
// speedup vs baseline: 1.2359x; 1.2359x over previous
#include <cuda_runtime.h>

// Deform_Conv_V1: fused offset-conv + deformable conv + ReLU.
// B=8, Cin=32, H=W=160, Cout=32, K=3, PAD=1.
// Inputs: x (8,32,160,160), w_off (18,32,3,3), b_off (18,), w_dcn (32,32,3,3)
// Output: (8,32,160,160) fp32.
//
// R10: split weight traffic across ports. Stage-1 w_off stays in __constant__
//      (LDC port); stage-2 w_dcn moves to shared memory (LDS broadcast via
//      L1tex). Keeps R7 wins: 2 px/thread, FFMA2, offset smem stash,
//      launch_bounds(128,4), fully-unrolled tap loops.

#define Hn  160
#define Wn  160
#define CIN 32
#define COUT 32
#define HWs (Hn * Wn)
#define NPIX (8 * HWs)

#define WDCN_T_ELEMS (9 * 32 * 32)   // [k][c][o]         = 9216
#define WOFF_T_ELEMS (9 * 32 * 20)   // [k][c][oc pad 20] = 5760

__constant__ float c_woff[WOFF_T_ELEMS];   // 22.5 KB
__device__ float g_stage[WOFF_T_ELEMS];

typedef unsigned long long u64;

// smem layout (dynamic): [0, 36864) wdcn_s [k][c][o]; [36864, 55296) offset stash
#define SMEM_WDCN  0
#define SMEM_STASH 36864
#define SMEM_TOTAL (36864 + 18432)

__device__ __forceinline__ u64 pack2(float a, float b) {
    u64 r; asm("mov.b64 %0, {%1, %2};" : "=l"(r) : "f"(a), "f"(b)); return r;
}
__device__ __forceinline__ void unpack2(u64 v, float& a, float& b) {
    asm("mov.b64 {%0, %1}, %2;" : "=f"(a), "=f"(b) : "l"(v));
}
__device__ __forceinline__ void ffma2(u64& d, u64 a, u64 b) {
    asm("fma.rn.f32x2 %0, %1, %2, %0;" : "+l"(d) : "l"(a), "l"(b));
}

__global__ void prep_kernel(const float* __restrict__ w_off)
{
    const int i = blockIdx.x * 256 + threadIdx.x;
    if (i < WOFF_T_ELEMS) {   // [k][c][oc pad 20]
        int k = i / 640;
        int r = i - k * 640;
        int c = r / 20;
        int oc = r - c * 20;
        g_stage[i] = (oc < 18) ? w_off[oc * 288 + c * 9 + k] : 0.0f;
    }
}

__global__ __launch_bounds__(128, 4)
void dcn_fused_kernel(const float* __restrict__ x,
                      const float* __restrict__ b_off,
                      const float* __restrict__ w_dcn,
                      float* __restrict__ out)
{
    extern __shared__ float smem[];
    float* wdcn_s = smem + SMEM_WDCN / 4;          // [9][32][32] (k, c, o)
    u64*   stash  = (u64*)((char*)smem + SMEM_STASH);

    const int tid = threadIdx.x;

    // Stage w_dcn transposed into shared memory (72 loads/thread, L2-hot).
    for (int i = tid; i < WDCN_T_ELEMS; i += 128) {
        int k = i >> 10;
        int r = i & 1023;
        int c = r >> 5;
        int o = r & 31;
        wdcn_s[i] = w_dcn[o * 288 + c * 9 + k];
    }
    __syncthreads();

    const int pairIdx = blockIdx.x * 128 + tid;   // 0 .. 102399
    const int PAIRS_PER_IMG = HWs / 2;            // 12800
    const int b   = pairIdx / PAIRS_PER_IMG;
    const int rem = pairIdx - b * PAIRS_PER_IMG;
    const int h   = rem / (Wn / 2);
    const int w0  = (rem - h * (Wn / 2)) * 2;
    const float* xb = x + (size_t)b * CIN * HWs;

    // ------------- Stage 1: offset conv (constant-port weights) -------------
    {
        u64 o2a[9], o2b[9];
#pragma unroll
        for (int p = 0; p < 9; p++) {
            u64 bv = pack2(__ldg(&b_off[2 * p]), __ldg(&b_off[2 * p + 1]));
            o2a[p] = bv;
            o2b[p] = bv;
        }

#pragma unroll
        for (int k = 0; k < 9; k++) {
            const int ky = k / 3;
            const int kx = k - 3 * ky;
            const int yy = h - 1 + ky;
            if (yy >= 0 && yy < Hn) {
                const int xx0 = w0 - 1 + kx;
                const int xx1 = xx0 + 1;
                const bool v0 = (xx0 >= 0) && (xx0 < Wn);
                const bool v1 = (xx1 >= 0) && (xx1 < Wn);
                const float* xr = xb + yy * Wn;
                const ulonglong2* wp = (const ulonglong2*)(c_woff + k * 640);
#pragma unroll 4
                for (int c = 0; c < CIN; c++) {
                    const float xv0 = v0 ? __ldg(xr + c * HWs + xx0) : 0.0f;
                    const float xv1 = v1 ? __ldg(xr + c * HWs + xx1) : 0.0f;
                    const u64 xa  = pack2(xv0, xv0);
                    const u64 xbv = pack2(xv1, xv1);
                    const ulonglong2* wc = wp + c * 5;
#pragma unroll
                    for (int j = 0; j < 4; j++) {
                        ulonglong2 q = wc[j];
                        ffma2(o2a[2 * j],     xa,  q.x);
                        ffma2(o2a[2 * j + 1], xa,  q.y);
                        ffma2(o2b[2 * j],     xbv, q.x);
                        ffma2(o2b[2 * j + 1], xbv, q.y);
                    }
                    ulonglong2 q4 = wc[4];
                    ffma2(o2a[8], xa,  q4.x);
                    ffma2(o2b[8], xbv, q4.x);
                }
            }
        }

#pragma unroll
        for (int p = 0; p < 9; p++) {
            stash[(0 * 128 + tid) * 9 + p] = o2a[p];
            stash[(1 * 128 + tid) * 9 + p] = o2b[p];
        }
    }

    // ------------- Stage 2: deformable conv (smem weights via LDS) -------------
    u64 acca[16], accb[16];
#pragma unroll
    for (int m = 0; m < 16; m++) { acca[m] = 0ULL; accb[m] = 0ULL; }

#pragma unroll
    for (int k = 0; k < 9; k++) {
        const int ky = k / 3;
        const int kx = k - 3 * ky;

        float aw00, aw01, aw10, aw11; int a00, a01, a10, a11;
        {
            float dy, dx; unpack2(stash[(0 * 128 + tid) * 9 + k], dy, dx);
            const float py = (float)(h - 1 + ky) + dy;
            const float px = (float)(w0 - 1 + kx) + dx;
            const float y0f = floorf(py), x0f = floorf(px);
            const float wy1 = py - y0f,  wx1 = px - x0f;
            const float wy0 = 1.0f - wy1, wx0 = 1.0f - wx1;
            const float y1f = y0f + 1.0f, x1f = x0f + 1.0f;
            const bool vy0 = (y0f >= 0.0f) && (y0f <= (float)(Hn - 1));
            const bool vy1 = (y1f >= 0.0f) && (y1f <= (float)(Hn - 1));
            const bool vx0 = (x0f >= 0.0f) && (x0f <= (float)(Wn - 1));
            const bool vx1 = (x1f >= 0.0f) && (x1f <= (float)(Wn - 1));
            aw00 = (vy0 && vx0) ? wy0 * wx0 : 0.0f;
            aw01 = (vy0 && vx1) ? wy0 * wx1 : 0.0f;
            aw10 = (vy1 && vx0) ? wy1 * wx0 : 0.0f;
            aw11 = (vy1 && vx1) ? wy1 * wx1 : 0.0f;
            const int iy0 = min(max((int)y0f, 0), Hn - 1);
            const int iy1 = min(max((int)y1f, 0), Hn - 1);
            const int ix0 = min(max((int)x0f, 0), Wn - 1);
            const int ix1 = min(max((int)x1f, 0), Wn - 1);
            a00 = iy0 * Wn + ix0; a01 = iy0 * Wn + ix1;
            a10 = iy1 * Wn + ix0; a11 = iy1 * Wn + ix1;
        }
        float bw00, bw01, bw10, bw11; int b00, b01, b10, b11;
        {
            float dy, dx; unpack2(stash[(1 * 128 + tid) * 9 + k], dy, dx);
            const float py = (float)(h - 1 + ky) + dy;
            const float px = (float)(w0 + kx) + dx;
            const float y0f = floorf(py), x0f = floorf(px);
            const float wy1 = py - y0f,  wx1 = px - x0f;
            const float wy0 = 1.0f - wy1, wx0 = 1.0f - wx1;
            const float y1f = y0f + 1.0f, x1f = x0f + 1.0f;
            const bool vy0 = (y0f >= 0.0f) && (y0f <= (float)(Hn - 1));
            const bool vy1 = (y1f >= 0.0f) && (y1f <= (float)(Hn - 1));
            const bool vx0 = (x0f >= 0.0f) && (x0f <= (float)(Wn - 1));
            const bool vx1 = (x1f >= 0.0f) && (x1f <= (float)(Wn - 1));
            bw00 = (vy0 && vx0) ? wy0 * wx0 : 0.0f;
            bw01 = (vy0 && vx1) ? wy0 * wx1 : 0.0f;
            bw10 = (vy1 && vx0) ? wy1 * wx0 : 0.0f;
            bw11 = (vy1 && vx1) ? wy1 * wx1 : 0.0f;
            const int iy0 = min(max((int)y0f, 0), Hn - 1);
            const int iy1 = min(max((int)y1f, 0), Hn - 1);
            const int ix0 = min(max((int)x0f, 0), Wn - 1);
            const int ix1 = min(max((int)x1f, 0), Wn - 1);
            b00 = iy0 * Wn + ix0; b01 = iy0 * Wn + ix1;
            b10 = iy1 * Wn + ix0; b11 = iy1 * Wn + ix1;
        }

        const u64 W00 = pack2(aw00, bw00);
        const u64 W01 = pack2(aw01, bw01);
        const u64 W10 = pack2(aw10, bw10);
        const u64 W11 = pack2(aw11, bw11);

        const ulonglong2* wp = (const ulonglong2*)(wdcn_s + k * 1024);
#pragma unroll 4
        for (int c = 0; c < CIN; c++) {
            const float* xc = xb + c * HWs;
            const u64 P00 = pack2(__ldg(xc + a00), __ldg(xc + b00));
            const u64 P01 = pack2(__ldg(xc + a01), __ldg(xc + b01));
            const u64 P10 = pack2(__ldg(xc + a10), __ldg(xc + b10));
            const u64 P11 = pack2(__ldg(xc + a11), __ldg(xc + b11));
            u64 vab = 0ULL;
            ffma2(vab, W00, P00);
            ffma2(vab, W01, P01);
            ffma2(vab, W10, P10);
            ffma2(vab, W11, P11);
            float va, vb; unpack2(vab, va, vb);
            const u64 va2 = pack2(va, va);
            const u64 vb2 = pack2(vb, vb);
            const ulonglong2* wc = wp + c * 8;
#pragma unroll
            for (int j = 0; j < 8; j++) {
                ulonglong2 q = wc[j];
                ffma2(acca[2 * j],     va2, q.x);
                ffma2(acca[2 * j + 1], va2, q.y);
                ffma2(accb[2 * j],     vb2, q.x);
                ffma2(accb[2 * j + 1], vb2, q.y);
            }
        }
    }

    // ------------- Epilogue: ReLU + coalesced float2 stores -------------
    float* ob = out + (size_t)b * COUT * HWs + h * Wn + w0;
#pragma unroll
    for (int m = 0; m < 16; m++) {
        float a0, a1, c0, c1;
        unpack2(acca[m], a0, a1);
        unpack2(accb[m], c0, c1);
        float2 r0, r1;
        r0.x = fmaxf(a0, 0.0f); r0.y = fmaxf(c0, 0.0f);
        r1.x = fmaxf(a1, 0.0f); r1.y = fmaxf(c1, 0.0f);
        *(float2*)(ob + (2 * m)     * HWs) = r0;
        *(float2*)(ob + (2 * m + 1) * HWs) = r1;
    }
}

extern "C" void kernel_launch(void* const* d_in, const int* in_sizes, int n_in,
                              void* d_out, int out_size)
{
    const float* x     = (const float*)d_in[0];
    const float* w_off = (const float*)d_in[1];
    const float* b_off = (const float*)d_in[2];
    const float* w_dcn = (const float*)d_in[3];
    float* out = (float*)d_out;

    void* stage_dev = nullptr;
    cudaGetSymbolAddress(&stage_dev, g_stage);

    prep_kernel<<<(WOFF_T_ELEMS + 255) / 256, 256>>>(w_off);
    cudaMemcpyToSymbolAsync(c_woff, stage_dev,
                            WOFF_T_ELEMS * sizeof(float), 0,
                            cudaMemcpyDeviceToDevice, 0);

    cudaFuncSetAttribute(dcn_fused_kernel,
                         cudaFuncAttributeMaxDynamicSharedMemorySize, SMEM_TOTAL);

    const int total_pairs = NPIX / 2;           // 102400
    const int threads = 128;
    const int blocks = total_pairs / threads;   // 800
    dcn_fused_kernel<<<blocks, threads, SMEM_TOTAL>>>(x, b_off, w_dcn, out);
}

// round 11
// speedup vs baseline: 1.6587x; 1.3421x over previous
#include <cuda_runtime.h>

// Deform_Conv_V1: fused offset-conv + deformable conv + ReLU.
// B=8, Cin=32, H=W=160, Cout=32, K=3, PAD=1.
// Inputs: x (8,32,160,160), w_off (18,32,3,3), b_off (18,), w_dcn (32,32,3,3)
// Output: (8,32,160,160) fp32.
//
// R11: stage-2 weights split across BOTH read ports: output channels 0-15 from
//      __constant__ (LDC port), channels 16-31 from smem (LDS/L1 port). Smem
//      kept to 36KB/CTA so 4 CTAs leave ~81KB L1D for gather caching (R10's
//      221KB smem starved L1D and regressed). Rest identical to R7.

#define Hn  160
#define Wn  160
#define CIN 32
#define COUT 32
#define HWs (Hn * Wn)
#define NPIX (8 * HWs)

#define WOFF_T_ELEMS  (9 * 32 * 20)   // [k][c][oc pad 20] = 5760
#define WDCNL_T_ELEMS (9 * 32 * 16)   // [k][c][o 0..15]   = 4608
#define WDCNH_T_ELEMS (9 * 32 * 16)   // [k][c][o 16..31]  = 4608

__constant__ float c_woff[WOFF_T_ELEMS];     // 22.5 KB
__constant__ float c_wdcn_lo[WDCNL_T_ELEMS]; // 18 KB
__device__ float g_stage[WOFF_T_ELEMS + WDCNL_T_ELEMS];

typedef unsigned long long u64;

// smem: [0, 18432) wdcn_hi [k][c][o16-31]; [18432, 36864) offset stash
#define SMEM_WHI   0
#define SMEM_STASH 18432
#define SMEM_TOTAL (18432 + 18432)

__device__ __forceinline__ u64 pack2(float a, float b) {
    u64 r; asm("mov.b64 %0, {%1, %2};" : "=l"(r) : "f"(a), "f"(b)); return r;
}
__device__ __forceinline__ void unpack2(u64 v, float& a, float& b) {
    asm("mov.b64 {%0, %1}, %2;" : "=f"(a), "=f"(b) : "l"(v));
}
__device__ __forceinline__ void ffma2(u64& d, u64 a, u64 b) {
    asm("fma.rn.f32x2 %0, %1, %2, %0;" : "+l"(d) : "l"(a), "l"(b));
}

__global__ void prep_kernel(const float* __restrict__ w_off,
                            const float* __restrict__ w_dcn)
{
    const int i = blockIdx.x * 256 + threadIdx.x;
    if (i < WOFF_T_ELEMS) {   // [k][c][oc pad 20]
        int k = i / 640;
        int r = i - k * 640;
        int c = r / 20;
        int oc = r - c * 20;
        g_stage[i] = (oc < 18) ? w_off[oc * 288 + c * 9 + k] : 0.0f;
    }
    if (i < WDCNL_T_ELEMS) {  // [k][c][o 0..15]
        int k = i / 512;
        int r = i - k * 512;
        int c = r >> 4;
        int o = r & 15;
        g_stage[WOFF_T_ELEMS + i] = w_dcn[o * 288 + c * 9 + k];
    }
}

__global__ __launch_bounds__(128, 4)
void dcn_fused_kernel(const float* __restrict__ x,
                      const float* __restrict__ b_off,
                      const float* __restrict__ w_dcn,
                      float* __restrict__ out)
{
    extern __shared__ float smem[];
    float* whi   = smem;                               // [9][32][16] (k,c,o16-31)
    u64*   stash = (u64*)((char*)smem + SMEM_STASH);

    const int tid = threadIdx.x;

    // Stage hi-half of w_dcn into smem (36 loads/thread, L2-hot).
    for (int i = tid; i < WDCNH_T_ELEMS; i += 128) {
        int k = i / 512;
        int r = i - k * 512;
        int c = r >> 4;
        int o = (r & 15) + 16;
        whi[i] = w_dcn[o * 288 + c * 9 + k];
    }
    __syncthreads();

    const int pairIdx = blockIdx.x * 128 + tid;   // 0 .. 102399
    const int PAIRS_PER_IMG = HWs / 2;            // 12800
    const int b   = pairIdx / PAIRS_PER_IMG;
    const int rem = pairIdx - b * PAIRS_PER_IMG;
    const int h   = rem / (Wn / 2);
    const int w0  = (rem - h * (Wn / 2)) * 2;
    const float* xb = x + (size_t)b * CIN * HWs;

    // ------------- Stage 1: offset conv (constant-port weights) -------------
    {
        u64 o2a[9], o2b[9];
#pragma unroll
        for (int p = 0; p < 9; p++) {
            u64 bv = pack2(__ldg(&b_off[2 * p]), __ldg(&b_off[2 * p + 1]));
            o2a[p] = bv;
            o2b[p] = bv;
        }

#pragma unroll
        for (int k = 0; k < 9; k++) {
            const int ky = k / 3;
            const int kx = k - 3 * ky;
            const int yy = h - 1 + ky;
            if (yy >= 0 && yy < Hn) {
                const int xx0 = w0 - 1 + kx;
                const int xx1 = xx0 + 1;
                const bool v0 = (xx0 >= 0) && (xx0 < Wn);
                const bool v1 = (xx1 >= 0) && (xx1 < Wn);
                const float* xr = xb + yy * Wn;
                const ulonglong2* wp = (const ulonglong2*)(c_woff + k * 640);
#pragma unroll 4
                for (int c = 0; c < CIN; c++) {
                    const float xv0 = v0 ? __ldg(xr + c * HWs + xx0) : 0.0f;
                    const float xv1 = v1 ? __ldg(xr + c * HWs + xx1) : 0.0f;
                    const u64 xa  = pack2(xv0, xv0);
                    const u64 xbv = pack2(xv1, xv1);
                    const ulonglong2* wc = wp + c * 5;
#pragma unroll
                    for (int j = 0; j < 4; j++) {
                        ulonglong2 q = wc[j];
                        ffma2(o2a[2 * j],     xa,  q.x);
                        ffma2(o2a[2 * j + 1], xa,  q.y);
                        ffma2(o2b[2 * j],     xbv, q.x);
                        ffma2(o2b[2 * j + 1], xbv, q.y);
                    }
                    ulonglong2 q4 = wc[4];
                    ffma2(o2a[8], xa,  q4.x);
                    ffma2(o2b[8], xbv, q4.x);
                }
            }
        }

#pragma unroll
        for (int p = 0; p < 9; p++) {
            stash[(0 * 128 + tid) * 9 + p] = o2a[p];
            stash[(1 * 128 + tid) * 9 + p] = o2b[p];
        }
    }

    // ------------- Stage 2: deformable conv (split-port weights) -------------
    u64 acca[16], accb[16];
#pragma unroll
    for (int m = 0; m < 16; m++) { acca[m] = 0ULL; accb[m] = 0ULL; }

#pragma unroll
    for (int k = 0; k < 9; k++) {
        const int ky = k / 3;
        const int kx = k - 3 * ky;

        float aw00, aw01, aw10, aw11; int a00, a01, a10, a11;
        {
            float dy, dx; unpack2(stash[(0 * 128 + tid) * 9 + k], dy, dx);
            const float py = (float)(h - 1 + ky) + dy;
            const float px = (float)(w0 - 1 + kx) + dx;
            const float y0f = floorf(py), x0f = floorf(px);
            const float wy1 = py - y0f,  wx1 = px - x0f;
            const float wy0 = 1.0f - wy1, wx0 = 1.0f - wx1;
            const float y1f = y0f + 1.0f, x1f = x0f + 1.0f;
            const bool vy0 = (y0f >= 0.0f) && (y0f <= (float)(Hn - 1));
            const bool vy1 = (y1f >= 0.0f) && (y1f <= (float)(Hn - 1));
            const bool vx0 = (x0f >= 0.0f) && (x0f <= (float)(Wn - 1));
            const bool vx1 = (x1f >= 0.0f) && (x1f <= (float)(Wn - 1));
            aw00 = (vy0 && vx0) ? wy0 * wx0 : 0.0f;
            aw01 = (vy0 && vx1) ? wy0 * wx1 : 0.0f;
            aw10 = (vy1 && vx0) ? wy1 * wx0 : 0.0f;
            aw11 = (vy1 && vx1) ? wy1 * wx1 : 0.0f;
            const int iy0 = min(max((int)y0f, 0), Hn - 1);
            const int iy1 = min(max((int)y1f, 0), Hn - 1);
            const int ix0 = min(max((int)x0f, 0), Wn - 1);
            const int ix1 = min(max((int)x1f, 0), Wn - 1);
            a00 = iy0 * Wn + ix0; a01 = iy0 * Wn + ix1;
            a10 = iy1 * Wn + ix0; a11 = iy1 * Wn + ix1;
        }
        float bw00, bw01, bw10, bw11; int b00, b01, b10, b11;
        {
            float dy, dx; unpack2(stash[(1 * 128 + tid) * 9 + k], dy, dx);
            const float py = (float)(h - 1 + ky) + dy;
            const float px = (float)(w0 + kx) + dx;
            const float y0f = floorf(py), x0f = floorf(px);
            const float wy1 = py - y0f,  wx1 = px - x0f;
            const float wy0 = 1.0f - wy1, wx0 = 1.0f - wx1;
            const float y1f = y0f + 1.0f, x1f = x0f + 1.0f;
            const bool vy0 = (y0f >= 0.0f) && (y0f <= (float)(Hn - 1));
            const bool vy1 = (y1f >= 0.0f) && (y1f <= (float)(Hn - 1));
            const bool vx0 = (x0f >= 0.0f) && (x0f <= (float)(Wn - 1));
            const bool vx1 = (x1f >= 0.0f) && (x1f <= (float)(Wn - 1));
            bw00 = (vy0 && vx0) ? wy0 * wx0 : 0.0f;
            bw01 = (vy0 && vx1) ? wy0 * wx1 : 0.0f;
            bw10 = (vy1 && vx0) ? wy1 * wx0 : 0.0f;
            bw11 = (vy1 && vx1) ? wy1 * wx1 : 0.0f;
            const int iy0 = min(max((int)y0f, 0), Hn - 1);
            const int iy1 = min(max((int)y1f, 0), Hn - 1);
            const int ix0 = min(max((int)x0f, 0), Wn - 1);
            const int ix1 = min(max((int)x1f, 0), Wn - 1);
            b00 = iy0 * Wn + ix0; b01 = iy0 * Wn + ix1;
            b10 = iy1 * Wn + ix0; b11 = iy1 * Wn + ix1;
        }

        const u64 W00 = pack2(aw00, bw00);
        const u64 W01 = pack2(aw01, bw01);
        const u64 W10 = pack2(aw10, bw10);
        const u64 W11 = pack2(aw11, bw11);

        const ulonglong2* wlo = (const ulonglong2*)(c_wdcn_lo + k * 512);
        const ulonglong2* whp = (const ulonglong2*)(whi + k * 512);
#pragma unroll 4
        for (int c = 0; c < CIN; c++) {
            const float* xc = xb + c * HWs;
            const u64 P00 = pack2(__ldg(xc + a00), __ldg(xc + b00));
            const u64 P01 = pack2(__ldg(xc + a01), __ldg(xc + b01));
            const u64 P10 = pack2(__ldg(xc + a10), __ldg(xc + b10));
            const u64 P11 = pack2(__ldg(xc + a11), __ldg(xc + b11));
            u64 vab = 0ULL;
            ffma2(vab, W00, P00);
            ffma2(vab, W01, P01);
            ffma2(vab, W10, P10);
            ffma2(vab, W11, P11);
            float va, vb; unpack2(vab, va, vb);
            const u64 va2 = pack2(va, va);
            const u64 vb2 = pack2(vb, vb);
#pragma unroll
            for (int j = 0; j < 4; j++) {          // o 0..15 via constant port
                ulonglong2 q = wlo[c * 4 + j];
                ffma2(acca[2 * j],     va2, q.x);
                ffma2(acca[2 * j + 1], va2, q.y);
                ffma2(accb[2 * j],     vb2, q.x);
                ffma2(accb[2 * j + 1], vb2, q.y);
            }
#pragma unroll
            for (int j = 0; j < 4; j++) {          // o 16..31 via smem/L1 port
                ulonglong2 q = whp[c * 4 + j];
                ffma2(acca[8 + 2 * j],     va2, q.x);
                ffma2(acca[8 + 2 * j + 1], va2, q.y);
                ffma2(accb[8 + 2 * j],     vb2, q.x);
                ffma2(accb[8 + 2 * j + 1], vb2, q.y);
            }
        }
    }

    // ------------- Epilogue: ReLU + coalesced float2 stores -------------
    // acc layout: acca[0..7] -> o 0..15, acca[8..15] -> o 16..31 (same order).
    float* ob = out + (size_t)b * COUT * HWs + h * Wn + w0;
#pragma unroll
    for (int m = 0; m < 16; m++) {
        float a0, a1, c0, c1;
        unpack2(acca[m], a0, a1);
        unpack2(accb[m], c0, c1);
        float2 r0, r1;
        r0.x = fmaxf(a0, 0.0f); r0.y = fmaxf(c0, 0.0f);
        r1.x = fmaxf(a1, 0.0f); r1.y = fmaxf(c1, 0.0f);
        *(float2*)(ob + (2 * m)     * HWs) = r0;
        *(float2*)(ob + (2 * m + 1) * HWs) = r1;
    }
}

extern "C" void kernel_launch(void* const* d_in, const int* in_sizes, int n_in,
                              void* d_out, int out_size)
{
    const float* x     = (const float*)d_in[0];
    const float* w_off = (const float*)d_in[1];
    const float* b_off = (const float*)d_in[2];
    const float* w_dcn = (const float*)d_in[3];
    float* out = (float*)d_out;

    void* stage_dev = nullptr;
    cudaGetSymbolAddress(&stage_dev, g_stage);

    prep_kernel<<<(WOFF_T_ELEMS + 255) / 256, 256>>>(w_off, w_dcn);
    cudaMemcpyToSymbolAsync(c_woff, stage_dev,
                            WOFF_T_ELEMS * sizeof(float), 0,
                            cudaMemcpyDeviceToDevice, 0);
    cudaMemcpyToSymbolAsync(c_wdcn_lo, (const char*)stage_dev + WOFF_T_ELEMS * sizeof(float),
                            WDCNL_T_ELEMS * sizeof(float), 0,
                            cudaMemcpyDeviceToDevice, 0);

    cudaFuncSetAttribute(dcn_fused_kernel,
                         cudaFuncAttributeMaxDynamicSharedMemorySize, SMEM_TOTAL);

    const int total_pairs = NPIX / 2;           // 102400
    const int threads = 128;
    const int blocks = total_pairs / threads;   // 800
    dcn_fused_kernel<<<blocks, threads, SMEM_TOTAL>>>(x, b_off, w_dcn, out);
}